// round 16
// baseline (speedup 1.0000x reference)
#include <cuda_runtime.h>
#include <cuda_bf16.h>
#include <mma.h>
#include <stdint.h>
#include <math.h>

using namespace nvcuda;

// Problem constants (AttentionLayer_11776800325798)
#define NMAX   50000
#define EMAX   500000
#define TT     3
#define RR     5
#define HH     8
#define DKK    16
#define FDIM   128
#define NRH    (NMAX * RR * HH)                      // 2,000,000
#define NL_CAP (((NMAX / 128) + TT + 1) * 128)       // 50432, 128-padded per type
#define SQRT_DK 4.0f
#define LDA 136                                      // bf16 elems per row (128 + 8 pad)
#define FLD 132                                      // fp32 staging tile stride
#define STG_LD 68                                    // wide staging stride (floats)
#define NSLOT 11                                     // q, k~ r0..4, v~ r0..4

// ---------------- scratch (static __device__, no allocation) ----------------
__device__ __nv_bfloat16 g_qb[NMAX * FDIM];
__device__ __nv_bfloat16 g_kt[(size_t)NMAX * RR * FDIM];   // k~ tables
__device__ __nv_bfloat16 g_vt[(size_t)NMAX * RR * FDIM];   // v~ tables
__device__ float    g_acc[NMAX * FDIM];
__device__ float    g_a[EMAX * HH];
__device__ float    g_den[NRH];
__device__ int      g_nlist[NL_CAP];
__device__ int      g_cur[TT];
__device__ int      g_poff[TT + 1];
// Wa split hi/lo for final (only set 3 used)
__device__ __align__(16) unsigned char g_wB[TT * 4 * 2 * 32768];
// fused weights [t][slot][128*128] bf16, slot: 0=Wq, 1..5=Wk@bd(A_r), 6..10=Wv@bd(M_r)
__device__ __align__(16) __nv_bfloat16 g_wfuse[TT * NSLOT * 16384];
__device__ float g_bfuse[TT * NSLOT * 128];

// fp32 -> bf16 hi + bf16 lo (packed pairs)
__device__ __forceinline__ uint32_t bfsplit(float a, float b, uint32_t& lo) {
    __nv_bfloat162 h = __floats2bfloat162_rn(a, b);
    float ra = a - __bfloat162float(h.x);
    float rb = b - __bfloat162float(h.y);
    __nv_bfloat162 l = __floats2bfloat162_rn(ra, rb);
    lo = *reinterpret_cast<uint32_t*>(&l);
    return *reinterpret_cast<uint32_t*>(&h);
}
__device__ __forceinline__ float2 bf2f2(uint32_t u) {
    __nv_bfloat162 b = *reinterpret_cast<__nv_bfloat162*>(&u);
    return __bfloat1622float2(b);
}
__device__ __forceinline__ uint32_t f2bf2(float a, float b) {
    __nv_bfloat162 p = __floats2bfloat162_rn(a, b);
    return *reinterpret_cast<uint32_t*>(&p);
}
__device__ __forceinline__ float dot8(uint4 a, uint4 b) {
    float2 a0 = bf2f2(a.x), a1 = bf2f2(a.y), a2 = bf2f2(a.z), a3 = bf2f2(a.w);
    float2 b0 = bf2f2(b.x), b1 = bf2f2(b.y), b2 = bf2f2(b.z), b3 = bf2f2(b.w);
    return a0.x * b0.x + a0.y * b0.y + a1.x * b1.x + a1.y * b1.y
         + a2.x * b2.x + a2.y * b2.y + a3.x * b3.x + a3.y * b3.y;
}

// ============================================================================
// K1: prep — counters + nlist init (1 block)
// ============================================================================
__global__ __launch_bounds__(1024) void prep_kernel(const int* __restrict__ ntype, int N) {
    __shared__ int scnt[TT];
    int tid = threadIdx.x;
    if (tid < TT) scnt[tid] = 0;
    __syncthreads();
    int c0 = 0, c1 = 0, c2 = 0;
    for (int i = tid; i < N; i += 1024) {
        int t = ntype[i];
        c0 += (t == 0); c1 += (t == 1); c2 += (t == 2);
    }
    if (c0) atomicAdd(&scnt[0], c0);
    if (c1) atomicAdd(&scnt[1], c1);
    if (c2) atomicAdd(&scnt[2], c2);
    __syncthreads();
    if (tid == 0) {
        int o = 0;
        for (int t = 0; t < TT; t++) { g_poff[t] = o; o += ((scnt[t] + 127) / 128) * 128; }
        g_poff[TT] = o;
    }
    if (tid < TT) g_cur[tid] = 0;
    for (int i = tid; i < NL_CAP; i += 1024) g_nlist[i] = -1;
}

// ============================================================================
// K2: COMBO — scatter + Wa hi/lo conv + fused weights/biases + zero
// ============================================================================
#define WA_N   (TT * 128 * 32)           // 12288 (Wa only)
#define WF_N   (TT * NSLOT * 128 * 128)  // 540672
#define BF_N   (TT * NSLOT * 128)        // 4224
__global__ void combo_kernel(const int* __restrict__ ntype, int N,
                             const float* __restrict__ Wk, const float* __restrict__ bk,
                             const float* __restrict__ Wq, const float* __restrict__ bq,
                             const float* __restrict__ Wv, const float* __restrict__ bv,
                             const float* __restrict__ Wa,
                             const float* __restrict__ rel_att, const float* __restrict__ rel_msg) {
    int gtid = blockIdx.x * 256 + threadIdx.x;
    int gstr = gridDim.x * 256;

    // --- section 1: node scatter ---
    {
        int i = gtid;
        int t = (i < N) ? ntype[i] : -1;
        #pragma unroll
        for (int tt = 0; tt < TT; tt++) {
            unsigned mask = __ballot_sync(0xFFFFFFFFu, t == tt);
            if (t == tt) {
                int lane = threadIdx.x & 31;
                int leader = __ffs(mask) - 1;
                int rank = __popc(mask & ((1u << lane) - 1));
                int base = 0;
                if (lane == leader) base = atomicAdd(&g_cur[tt], __popc(mask));
                base = __shfl_sync(mask, base, leader);
                g_nlist[g_poff[tt] + base + rank] = i;
            }
        }
    }

    // --- section 2: Wa -> bf16 hi/lo (into g_wB slot set=3) ---
    for (int idx = gtid; idx < WA_N; idx += gstr) {
        int c = (idx & 31) * 4;
        int kk = (idx >> 5) & 127;
        int t = idx >> 12;
        const float* W = Wa + t * FDIM * FDIM;
        float4 f = *(const float4*)(W + kk * FDIM + c);
        uint32_t l0, l1;
        uint32_t h0 = bfsplit(f.x, f.y, l0), h1 = bfsplit(f.z, f.w, l1);
        __nv_bfloat16* hi = (__nv_bfloat16*)(g_wB + (size_t)(t * 4 + 3) * 65536);
        __nv_bfloat16* lo = hi + 128 * 128;
        *(uint32_t*)(hi + kk * 128 + c)     = h0;
        *(uint32_t*)(hi + kk * 128 + c + 2) = h1;
        *(uint32_t*)(lo + kk * 128 + c)     = l0;
        *(uint32_t*)(lo + kk * 128 + c + 2) = l1;
    }

    // --- section 3: fused weights: slot0 = Wq, 1..5 = Wk@bd(A_r), 6..10 = Wv@bd(M_r) ---
    for (int idx = gtid; idx < WF_N; idx += gstr) {
        int n = idx & 127;
        int kk = (idx >> 7) & 127;
        int g = idx >> 14;                 // t*NSLOT + slot
        int slot = g % NSLOT, t = g / NSLOT;
        float val;
        if (slot == 0) {
            val = Wq[t * 16384 + kk * 128 + n];
        } else {
            int isK = (slot <= 5);
            int r = isK ? (slot - 1) : (slot - 6);
            const float* W   = isK ? Wk : Wv;
            const float* rel = isK ? rel_att : rel_msg;
            int h = n >> 4, j = n & 15;
            const float* wrow = W + t * 16384 + kk * 128 + h * 16;
            const float* rcol = rel + ((r * HH + h) * 16) * 16 + j;
            float s = 0.f;
            #pragma unroll
            for (int d = 0; d < 16; d++) s = fmaf(wrow[d], rcol[d * 16], s);
            val = s;
        }
        g_wfuse[(size_t)g * 16384 + kk * 128 + n] = __float2bfloat16(val);
    }

    // --- section 4: fused biases ---
    for (int idx = gtid; idx < BF_N; idx += gstr) {
        int n = idx & 127;
        int g = idx >> 7;
        int slot = g % NSLOT, t = g / NSLOT;
        float val;
        if (slot == 0) {
            val = bq[t * 128 + n];
        } else {
            int isK = (slot <= 5);
            int r = isK ? (slot - 1) : (slot - 6);
            const float* b   = isK ? bk : bv;
            const float* rel = isK ? rel_att : rel_msg;
            int h = n >> 4, j = n & 15;
            float s = 0.f;
            #pragma unroll
            for (int d = 0; d < 16; d++)
                s = fmaf(b[t * 128 + h * 16 + d], rel[((r * HH + h) * 16 + d) * 16 + j], s);
            val = s;
        }
        g_bfuse[g * 128 + n] = val;
    }

    // --- section 5: zero g_acc / g_den ---
    for (int idx = gtid; idx < NMAX * FDIM; idx += gstr) {
        g_acc[idx] = 0.f;
        if (idx < NRH) g_den[idx] = 0.f;
    }
}

// ============================================================================
// K3: 11 fused GEMMs per 128-node tile -> q / k~ / v~ directly.
// ============================================================================
__global__ __launch_bounds__(256, 2) void proj_wmma_kernel(
    const float* __restrict__ x, const int* __restrict__ ntype)
{
    extern __shared__ __align__(16) char dynsm[];
    __nv_bfloat16* Ah = (__nv_bfloat16*)dynsm;                 // [128][LDA]
    __shared__ int s_nl[128];
    __shared__ int s_t;
    __shared__ __align__(16) float stg[8][16][STG_LD];

    int tid = threadIdx.x, w = tid >> 5, lane = tid & 31;
    if (tid < 128) s_nl[tid] = g_nlist[blockIdx.x * 128 + tid];
    __syncthreads();
    if (tid == 0) {
        int t = -1;
        for (int m = 0; m < 128; m++) if (s_nl[m] >= 0) { t = ntype[s_nl[m]]; break; }
        s_t = t;
    }
    __syncthreads();
    if (s_t < 0) return;

    // stage A: gather x rows -> bf16
    for (int idx = tid; idx < 128 * 32; idx += 256) {
        int m = idx >> 5, c = (idx & 31) * 4;
        int n = s_nl[m];
        float4 f = (n >= 0) ? *(const float4*)(x + (size_t)n * FDIM + c)
                            : make_float4(0.f, 0.f, 0.f, 0.f);
        *(uint32_t*)(Ah + m * LDA + c)     = f2bf2(f.x, f.y);
        *(uint32_t*)(Ah + m * LDA + c + 2) = f2bf2(f.z, f.w);
    }
    __syncthreads();

    int rg = w & 3, cg = w >> 2;
    int row_m = rg * 32;
    int colb = cg * 64;

    for (int gi = 0; gi < NSLOT; gi++) {
        const __nv_bfloat16* GB = g_wfuse + (size_t)(s_t * NSLOT + gi) * 16384;
        const float* bias = g_bfuse + (s_t * NSLOT + gi) * 128;

        wmma::fragment<wmma::accumulator, 16, 16, 16, float> acc[2][4];
        #pragma unroll
        for (int mi = 0; mi < 2; mi++)
            #pragma unroll
            for (int ni = 0; ni < 4; ni++) wmma::fill_fragment(acc[mi][ni], 0.f);

        #pragma unroll
        for (int k = 0; k < 8; k++) {
            wmma::fragment<wmma::matrix_a, 16, 16, 16, __nv_bfloat16, wmma::row_major> ah0, ah1;
            wmma::load_matrix_sync(ah0, Ah + (row_m +  0) * LDA + k * 16, LDA);
            wmma::load_matrix_sync(ah1, Ah + (row_m + 16) * LDA + k * 16, LDA);
            #pragma unroll
            for (int ni = 0; ni < 4; ni++) {
                wmma::fragment<wmma::matrix_b, 16, 16, 16, __nv_bfloat16, wmma::row_major> bh;
                wmma::load_matrix_sync(bh, GB + (k * 16) * 128 + colb + ni * 16, 128);
                wmma::mma_sync(acc[0][ni], ah0, bh, acc[0][ni]);
                wmma::mma_sync(acc[1][ni], ah1, bh, acc[1][ni]);
            }
        }

        // batched epilogue: 4 tiles -> wide staging -> 64B per lane, bias fused
        #pragma unroll
        for (int mi = 0; mi < 2; mi++) {
            #pragma unroll
            for (int ni = 0; ni < 4; ni++)
                wmma::store_matrix_sync(&stg[w][0][ni * 16], acc[mi][ni], STG_LD, wmma::mem_row_major);
            __syncwarp();
            int grow = lane >> 1, ghalf = lane & 1;
            int gr = s_nl[row_m + mi * 16 + grow];
            if (gr >= 0) {
                __nv_bfloat16* drow;
                if (gi == 0)      drow = g_qb + (size_t)gr * FDIM;
                else if (gi <= 5) drow = g_kt + ((size_t)gr * RR + (gi - 1)) * FDIM;
                else              drow = g_vt + ((size_t)gr * RR + (gi - 6)) * FDIM;
                drow += colb + ghalf * 32;
                const float* Sr = &stg[w][grow][ghalf * 32];
                const float* bb = bias + colb + ghalf * 32;
                #pragma unroll
                for (int u = 0; u < 4; u++) {
                    float4 f0 = *(const float4*)(Sr + u * 8);
                    float4 f1 = *(const float4*)(Sr + u * 8 + 4);
                    float4 b0 = *(const float4*)(bb + u * 8);
                    float4 b1 = *(const float4*)(bb + u * 8 + 4);
                    f0.x += b0.x; f0.y += b0.y; f0.z += b0.z; f0.w += b0.w;
                    f1.x += b1.x; f1.y += b1.y; f1.z += b1.z; f1.w += b1.w;
                    *(uint4*)(drow + u * 8) = make_uint4(f2bf2(f0.x, f0.y), f2bf2(f0.z, f0.w),
                                                         f2bf2(f1.x, f1.y), f2bf2(f1.z, f1.w));
                }
            }
            __syncwarp();
        }
    }
}

// ============================================================================
// K4: edge scores. Half-warp per edge, unroll x2.          [PROFILED SLOT #4]
// ============================================================================
__global__ __launch_bounds__(256) void score2_kernel(
    const int* __restrict__ src, const int* __restrict__ dst,
    const int* __restrict__ etype, const float* __restrict__ rel_pri, int E) {
    __shared__ float s_pri[RR * HH];
    if (threadIdx.x < RR * HH) s_pri[threadIdx.x] = rel_pri[threadIdx.x] * (1.0f / SQRT_DK);
    __syncthreads();

    int warp = threadIdx.x >> 5;
    int lane = threadIdx.x & 31;
    int sub = lane >> 4;
    int l = lane & 15;
    int h = l >> 1, half = l & 1;
    int off = h * DKK + half * 8;

    int base = (blockIdx.x * 8 + warp) * 4;
    int stride = gridDim.x * 32;
    for (int e0 = base; e0 < E; e0 += stride) {
        int eA = e0 + sub * 2;
        int eB = eA + 1;
        bool vA = (eA < E), vB = (eB < E);
        int ecA = vA ? eA : (E - 1);
        int ecB = vB ? eB : (E - 1);
        int sA = src[ecA], dA = dst[ecA], rA = etype[ecA];
        int sB = src[ecB], dB = dst[ecB], rB = etype[ecB];
        uint4 kuA = *(const uint4*)(g_kt + ((size_t)sA * RR + rA) * FDIM + off);
        uint4 quA = *(const uint4*)(g_qb + (size_t)dA * FDIM + off);
        uint4 kuB = *(const uint4*)(g_kt + ((size_t)sB * RR + rB) * FDIM + off);
        uint4 quB = *(const uint4*)(g_qb + (size_t)dB * FDIM + off);
        float scA = dot8(kuA, quA);
        float scB = dot8(kuB, quB);
        scA += __shfl_xor_sync(0xFFFFFFFFu, scA, 1);
        scB += __shfl_xor_sync(0xFFFFFFFFu, scB, 1);
        scA *= s_pri[rA * HH + h];
        scB *= s_pri[rB * HH + h];
        if (half == 0) {
            if (vA) {
                float p = __expf(scA);
                g_a[eA * HH + h] = p;
                atomicAdd(&g_den[(dA * RR + rA) * HH + h], p);
            }
            if (vB) {
                float p = __expf(scB);
                g_a[eB * HH + h] = p;
                atomicAdd(&g_den[(dB * RR + rB) * HH + h], p);
            }
        }
    }
}

// ============================================================================
// K5: aggregation. Half-warp per edge, unroll x2.
// ============================================================================
__global__ __launch_bounds__(256) void agg2_kernel(
    const int* __restrict__ src, const int* __restrict__ dst,
    const int* __restrict__ etype, int E) {
    int warp = threadIdx.x >> 5;
    int lane = threadIdx.x & 31;
    int sub = lane >> 4;
    int l = lane & 15;
    int h = l >> 1, half = l & 1;
    int off = h * DKK + half * 8;

    int base = (blockIdx.x * 8 + warp) * 4;
    int stride = gridDim.x * 32;
    for (int e0 = base; e0 < E; e0 += stride) {
        int eA = e0 + sub * 2;
        int eB = eA + 1;
        bool vA = (eA < E), vB = (eB < E);
        int ecA = vA ? eA : (E - 1);
        int ecB = vB ? eB : (E - 1);
        int sA = src[ecA], dA = dst[ecA], rA = etype[ecA];
        int sB = src[ecB], dB = dst[ecB], rB = etype[ecB];
        float pA = g_a[ecA * HH + h];
        float pB = g_a[ecB * HH + h];
        uint4 vuA = *(const uint4*)(g_vt + ((size_t)sA * RR + rA) * FDIM + off);
        uint4 vuB = *(const uint4*)(g_vt + ((size_t)sB * RR + rB) * FDIM + off);
        float denA = g_den[(dA * RR + rA) * HH + h];
        float denB = g_den[(dB * RR + rB) * HH + h];
        float awA = pA / denA;
        float awB = pB / denB;
        if (vA) {
            float2 v0 = bf2f2(vuA.x), v1 = bf2f2(vuA.y), v2 = bf2f2(vuA.z), v3 = bf2f2(vuA.w);
            float* dp = g_acc + (size_t)dA * FDIM + off;
            atomicAdd((float4*)dp,       make_float4(awA*v0.x, awA*v0.y, awA*v1.x, awA*v1.y));
            atomicAdd((float4*)(dp + 4), make_float4(awA*v2.x, awA*v2.y, awA*v3.x, awA*v3.y));
        }
        if (vB) {
            float2 v0 = bf2f2(vuB.x), v1 = bf2f2(vuB.y), v2 = bf2f2(vuB.z), v3 = bf2f2(vuB.w);
            float* dp = g_acc + (size_t)dB * FDIM + off;
            atomicAdd((float4*)dp,       make_float4(awB*v0.x, awB*v0.y, awB*v1.x, awB*v1.y));
            atomicAdd((float4*)(dp + 4), make_float4(awB*v2.x, awB*v2.y, awB*v3.x, awB*v3.y));
        }
    }
}

// ============================================================================
// K6: mean-over-etypes, Wa proj (wmma split-bf16), skip blend, per-type LN
// ============================================================================
__global__ __launch_bounds__(256) void final_wmma_kernel(
    const float* __restrict__ x, const int* __restrict__ ntype,
    const float* __restrict__ ba, const float* __restrict__ skipv,
    const float* __restrict__ ln_g, const float* __restrict__ ln_b,
    float* __restrict__ out)
{
    extern __shared__ __align__(16) char dynsm[];
    __nv_bfloat16* Ah = (__nv_bfloat16*)dynsm;
    __nv_bfloat16* Al = Ah + 128 * LDA;
    float* F = (float*)dynsm;                 // fp32 tile [128][FLD]; aliased AFTER GEMM
    __shared__ int s_nl[128];
    __shared__ int s_t;
    __shared__ float s_scp[128];

    int tid = threadIdx.x, w = tid >> 5, lane = tid & 31;
    if (tid < 128) s_nl[tid] = g_nlist[blockIdx.x * 128 + tid];
    __syncthreads();
    if (tid == 0) {
        int t = -1;
        for (int m = 0; m < 128; m++) if (s_nl[m] >= 0) { t = ntype[s_nl[m]]; break; }
        s_t = t;
    }
    if (tid < 128) {
        int n = s_nl[tid];
        float inv = 1.f;
        if (n >= 0) {
            int cp = 0;
            for (int r = 0; r < RR; r++) cp += (g_den[(n * RR + r) * HH] > 0.f) ? 1 : 0;
            if (cp < 1) cp = 1;
            inv = 1.f / (float)cp;
        }
        s_scp[tid] = inv;
    }
    __syncthreads();
    if (s_t < 0) return;

    for (int idx = tid; idx < 128 * 32; idx += 256) {
        int m = idx >> 5, c = (idx & 31) * 4;
        int n = s_nl[m];
        float4 f = make_float4(0.f, 0.f, 0.f, 0.f);
        if (n >= 0) {
            f = *(const float4*)(g_acc + (size_t)n * FDIM + c);
            float sc = s_scp[m];
            f.x *= sc; f.y *= sc; f.z *= sc; f.w *= sc;
        }
        uint32_t l0, l1;
        uint32_t h0 = bfsplit(f.x, f.y, l0), h1 = bfsplit(f.z, f.w, l1);
        *(uint32_t*)(Ah + m * LDA + c)     = h0;
        *(uint32_t*)(Ah + m * LDA + c + 2) = h1;
        *(uint32_t*)(Al + m * LDA + c)     = l0;
        *(uint32_t*)(Al + m * LDA + c + 2) = l1;
    }
    __syncthreads();

    int rg = w & 3, cg = w >> 2;
    int row_m = rg * 32;
    int colb = cg * 64;
    const __nv_bfloat16* GBh = (const __nv_bfloat16*)(g_wB + (size_t)(s_t * 4 + 3) * 65536);
    const __nv_bfloat16* GBl = GBh + 128 * 128;

    wmma::fragment<wmma::accumulator, 16, 16, 16, float> acc[2][4];
    #pragma unroll
    for (int mi = 0; mi < 2; mi++)
        #pragma unroll
        for (int ni = 0; ni < 4; ni++) wmma::fill_fragment(acc[mi][ni], 0.f);

    #pragma unroll
    for (int k = 0; k < 8; k++) {
        wmma::fragment<wmma::matrix_a, 16, 16, 16, __nv_bfloat16, wmma::row_major> ah0, ah1, al0, al1;
        wmma::load_matrix_sync(ah0, Ah + (row_m +  0) * LDA + k * 16, LDA);
        wmma::load_matrix_sync(ah1, Ah + (row_m + 16) * LDA + k * 16, LDA);
        wmma::load_matrix_sync(al0, Al + (row_m +  0) * LDA + k * 16, LDA);
        wmma::load_matrix_sync(al1, Al + (row_m + 16) * LDA + k * 16, LDA);
        #pragma unroll
        for (int ni = 0; ni < 4; ni++) {
            wmma::fragment<wmma::matrix_b, 16, 16, 16, __nv_bfloat16, wmma::row_major> bh, bl;
            wmma::load_matrix_sync(bh, GBh + (k * 16) * 128 + colb + ni * 16, 128);
            wmma::load_matrix_sync(bl, GBl + (k * 16) * 128 + colb + ni * 16, 128);
            wmma::mma_sync(acc[0][ni], ah0, bh, acc[0][ni]);
            wmma::mma_sync(acc[0][ni], ah0, bl, acc[0][ni]);
            wmma::mma_sync(acc[0][ni], al0, bh, acc[0][ni]);
            wmma::mma_sync(acc[1][ni], ah1, bh, acc[1][ni]);
            wmma::mma_sync(acc[1][ni], ah1, bl, acc[1][ni]);
            wmma::mma_sync(acc[1][ni], al1, bh, acc[1][ni]);
        }
    }
    __syncthreads();

    #pragma unroll
    for (int mi = 0; mi < 2; mi++)
        #pragma unroll
        for (int ni = 0; ni < 4; ni++)
            wmma::store_matrix_sync(F + (row_m + mi * 16) * FLD + colb + ni * 16,
                                    acc[mi][ni], FLD, wmma::mem_row_major);
    __syncthreads();

    float alpha = 1.f / (1.f + __expf(-skipv[s_t]));
    float beta = 1.f - alpha;
    int c0 = lane * 4;
    float4 bav = *(const float4*)(ba   + s_t * FDIM + c0);
    float4 gv  = *(const float4*)(ln_g + s_t * FDIM + c0);
    float4 bv2 = *(const float4*)(ln_b + s_t * FDIM + c0);
    int rbase = w * 16;
    for (int q = 0; q < 16; q++) {
        int m = rbase + q;
        int n = s_nl[m];
        if (n < 0) continue;
        float4 tr = *(float4*)(F + m * FLD + c0);
        float4 xv = *(const float4*)(x + (size_t)n * FDIM + c0);
        float4 v;
        v.x = (tr.x + bav.x) * alpha + xv.x * beta;
        v.y = (tr.y + bav.y) * alpha + xv.y * beta;
        v.z = (tr.z + bav.z) * alpha + xv.z * beta;
        v.w = (tr.w + bav.w) * alpha + xv.w * beta;
        float s  = v.x + v.y + v.z + v.w;
        float s2 = v.x*v.x + v.y*v.y + v.z*v.z + v.w*v.w;
        #pragma unroll
        for (int o = 16; o; o >>= 1) {
            s  += __shfl_xor_sync(0xFFFFFFFFu, s,  o);
            s2 += __shfl_xor_sync(0xFFFFFFFFu, s2, o);
        }
        float mu = s * (1.f / 128.f);
        float var = s2 * (1.f / 128.f) - mu * mu;
        float rstd = rsqrtf(var + 1e-5f);
        float4 ov;
        ov.x = (v.x - mu) * rstd * gv.x + bv2.x;
        ov.y = (v.y - mu) * rstd * gv.y + bv2.y;
        ov.z = (v.z - mu) * rstd * gv.z + bv2.z;
        ov.w = (v.w - mu) * rstd * gv.w + bv2.w;
        *(float4*)(out + (size_t)n * FDIM + c0) = ov;
    }
}

// ---------------- launch ----------------
extern "C" void kernel_launch(void* const* d_in, const int* in_sizes, int n_in,
                              void* d_out, int out_size) {
    const float* x       = (const float*)d_in[0];
    const int*   ntype   = (const int*)  d_in[1];
    const int*   src     = (const int*)  d_in[2];
    const int*   dst     = (const int*)  d_in[3];
    const int*   etype   = (const int*)  d_in[4];
    const float* Wk      = (const float*)d_in[5];
    const float* bk      = (const float*)d_in[6];
    const float* Wq      = (const float*)d_in[7];
    const float* bq      = (const float*)d_in[8];
    const float* Wv      = (const float*)d_in[9];
    const float* bv      = (const float*)d_in[10];
    const float* Wa      = (const float*)d_in[11];
    const float* ba      = (const float*)d_in[12];
    const float* rel_pri = (const float*)d_in[13];
    const float* rel_att = (const float*)d_in[14];
    const float* rel_msg = (const float*)d_in[15];
    const float* skipv   = (const float*)d_in[16];
    const float* ln_g    = (const float*)d_in[17];
    const float* ln_b    = (const float*)d_in[18];
    float* out = (float*)d_out;

    const int N = in_sizes[1];
    const int E = in_sizes[2];
    const int PROJ_SMEM = 128 * LDA * 2;               // 34816 B (Ah only)
    const int A_SMEM = 2 * 128 * LDA * 2;              // 69632 B
    const int F_SMEM = 128 * FLD * 4;                  // 67584 B
    const int FIN_SMEM = (A_SMEM > F_SMEM) ? A_SMEM : F_SMEM;

    cudaFuncSetAttribute(proj_wmma_kernel,  cudaFuncAttributeMaxDynamicSharedMemorySize, PROJ_SMEM);
    cudaFuncSetAttribute(final_wmma_kernel, cudaFuncAttributeMaxDynamicSharedMemorySize, FIN_SMEM);

    prep_kernel<<<1, 1024>>>(ntype, N);
    combo_kernel<<<2048, 256>>>(ntype, N, Wk, bk, Wq, bq, Wv, bv, Wa, rel_att, rel_msg);
    proj_wmma_kernel<<<NL_CAP / 128, 256, PROJ_SMEM>>>(x, ntype);
    score2_kernel<<<2048, 256>>>(src, dst, etype, rel_pri, E);   // profiled slot #4
    agg2_kernel<<<2048, 256>>>(src, dst, etype, E);
    final_wmma_kernel<<<NL_CAP / 128, 256, FIN_SMEM>>>(x, ntype, ba, skipv, ln_g, ln_b, out);
}

// round 17
// speedup vs baseline: 1.3203x; 1.3203x over previous
#include <cuda_runtime.h>
#include <cuda_bf16.h>
#include <mma.h>
#include <stdint.h>
#include <math.h>

using namespace nvcuda;

// Problem constants (AttentionLayer_11776800325798)
#define NMAX   50000
#define EMAX   500000
#define TT     3
#define RR     5
#define HH     8
#define DKK    16
#define FDIM   128
#define NRH    (NMAX * RR * HH)                      // 2,000,000
#define NL_CAP (((NMAX / 128) + TT + 1) * 128)       // 50432, 128-padded per type
#define SQRT_DK 4.0f
#define LDA 136                                      // bf16 elems per row (128 + 8 pad)
#define FLD 132                                      // fp32 staging tile stride
#define STG_LD 68                                    // wide staging stride (floats)

// ---------------- scratch (static __device__, no allocation) ----------------
__device__ __nv_bfloat16 g_qb[NMAX * FDIM];
__device__ __nv_bfloat16 g_kt[(size_t)NMAX * RR * FDIM];   // k~ = k @ bd(rel_att[r])
__device__ __nv_bfloat16 g_vt[(size_t)NMAX * RR * FDIM];   // v~ = v @ bd(rel_msg[r])
__device__ float    g_acc[NMAX * FDIM];
__device__ float    g_a[EMAX * HH];
__device__ float    g_den[NRH];
__device__ int      g_nlist[NL_CAP];
__device__ int      g_cur[TT];
__device__ int      g_poff[TT + 1];
// pre-converted weights: [type][set(k,q,v,a)][hi|lo] each 128x128 bf16 row-major (32KB)
__device__ __align__(16) unsigned char g_wB[TT * 4 * 2 * 32768];
// bf16 relation blocks [r][h][16][16]
__device__ __align__(16) __nv_bfloat16 g_relab[RR * HH * 256];
__device__ __align__(16) __nv_bfloat16 g_relmb[RR * HH * 256];

// fp32 -> bf16 hi + bf16 lo (packed pairs)
__device__ __forceinline__ uint32_t bfsplit(float a, float b, uint32_t& lo) {
    __nv_bfloat162 h = __floats2bfloat162_rn(a, b);
    float ra = a - __bfloat162float(h.x);
    float rb = b - __bfloat162float(h.y);
    __nv_bfloat162 l = __floats2bfloat162_rn(ra, rb);
    lo = *reinterpret_cast<uint32_t*>(&l);
    return *reinterpret_cast<uint32_t*>(&h);
}
__device__ __forceinline__ float2 bf2f2(uint32_t u) {
    __nv_bfloat162 b = *reinterpret_cast<__nv_bfloat162*>(&u);
    return __bfloat1622float2(b);
}
__device__ __forceinline__ uint32_t f2bf2(float a, float b) {
    __nv_bfloat162 p = __floats2bfloat162_rn(a, b);
    return *reinterpret_cast<uint32_t*>(&p);
}
__device__ __forceinline__ float dot8(uint4 a, uint4 b) {
    float2 a0 = bf2f2(a.x), a1 = bf2f2(a.y), a2 = bf2f2(a.z), a3 = bf2f2(a.w);
    float2 b0 = bf2f2(b.x), b1 = bf2f2(b.y), b2 = bf2f2(b.z), b3 = bf2f2(b.w);
    return a0.x * b0.x + a0.y * b0.y + a1.x * b1.x + a1.y * b1.y
         + a2.x * b2.x + a2.y * b2.y + a3.x * b3.x + a3.y * b3.y;
}

// ============================================================================
// K1: prep — counters + nlist init (1 block)
// ============================================================================
__global__ __launch_bounds__(1024) void prep_kernel(const int* __restrict__ ntype, int N) {
    __shared__ int scnt[TT];
    int tid = threadIdx.x;
    if (tid < TT) scnt[tid] = 0;
    __syncthreads();
    int c0 = 0, c1 = 0, c2 = 0;
    for (int i = tid; i < N; i += 1024) {
        int t = ntype[i];
        c0 += (t == 0); c1 += (t == 1); c2 += (t == 2);
    }
    if (c0) atomicAdd(&scnt[0], c0);
    if (c1) atomicAdd(&scnt[1], c1);
    if (c2) atomicAdd(&scnt[2], c2);
    __syncthreads();
    if (tid == 0) {
        int o = 0;
        for (int t = 0; t < TT; t++) { g_poff[t] = o; o += ((scnt[t] + 127) / 128) * 128; }
        g_poff[TT] = o;
    }
    if (tid < TT) g_cur[tid] = 0;
    for (int i = tid; i < NL_CAP; i += 1024) g_nlist[i] = -1;
}

// ============================================================================
// K2: COMBO — scatter (first blocks) + wconv/relconv + zero (grid-stride)
// ============================================================================
#define WCONV_N (TT * 4 * 128 * 32)      // 49152
#define RCONV_N (RR * HH * 128)          // 5120
__global__ void combo_kernel(const int* __restrict__ ntype, int N,
                             const float* __restrict__ Wk, const float* __restrict__ Wq,
                             const float* __restrict__ Wv, const float* __restrict__ Wa,
                             const float* __restrict__ rel_att, const float* __restrict__ rel_msg) {
    int gtid = blockIdx.x * 256 + threadIdx.x;
    int gstr = gridDim.x * 256;

    // --- section 1: node scatter (first ceil(N/256) blocks) ---
    {
        int i = gtid;
        int t = (i < N) ? ntype[i] : -1;
        #pragma unroll
        for (int tt = 0; tt < TT; tt++) {
            unsigned mask = __ballot_sync(0xFFFFFFFFu, t == tt);
            if (t == tt) {
                int lane = threadIdx.x & 31;
                int leader = __ffs(mask) - 1;
                int rank = __popc(mask & ((1u << lane) - 1));
                int base = 0;
                if (lane == leader) base = atomicAdd(&g_cur[tt], __popc(mask));
                base = __shfl_sync(mask, base, leader);
                g_nlist[g_poff[tt] + base + rank] = i;
            }
        }
    }

    // --- section 2: weight + relation conversion ---
    for (int idx = gtid; idx < WCONV_N + RCONV_N; idx += gstr) {
        if (idx < WCONV_N) {
            int c = (idx & 31) * 4;
            int kk = (idx >> 5) & 127;
            int g = idx >> 12;
            int set = g & 3, t = g >> 2;
            const float* W = ((set == 0) ? Wk : (set == 1) ? Wq : (set == 2) ? Wv : Wa) + t * FDIM * FDIM;
            float4 f = *(const float4*)(W + kk * FDIM + c);
            uint32_t l0, l1;
            uint32_t h0 = bfsplit(f.x, f.y, l0), h1 = bfsplit(f.z, f.w, l1);
            __nv_bfloat16* hi = (__nv_bfloat16*)(g_wB + (size_t)g * 65536);
            __nv_bfloat16* lo = hi + 128 * 128;
            *(uint32_t*)(hi + kk * 128 + c)     = h0;
            *(uint32_t*)(hi + kk * 128 + c + 2) = h1;
            *(uint32_t*)(lo + kk * 128 + c)     = l0;
            *(uint32_t*)(lo + kk * 128 + c + 2) = l1;
        } else {
            int i = idx - WCONV_N;
            float2 fa = *(const float2*)(rel_att + i * 2);
            float2 fm = *(const float2*)(rel_msg + i * 2);
            *(uint32_t*)(g_relab + i * 2) = f2bf2(fa.x, fa.y);
            *(uint32_t*)(g_relmb + i * 2) = f2bf2(fm.x, fm.y);
        }
    }

    // --- section 3: zero g_acc / g_den ---
    for (int idx = gtid; idx < NMAX * FDIM; idx += gstr) {
        g_acc[idx] = 0.f;
        if (idx < NRH) g_den[idx] = 0.f;
    }
}

// ============================================================================
// K3: typed projections + fused k~/v~ tables (batched epilogue, hoisted A-frags).
// ============================================================================
__global__ __launch_bounds__(256, 2) void proj_wmma_kernel(
    const float* __restrict__ x, const int* __restrict__ ntype,
    const float* __restrict__ bk, const float* __restrict__ bq,
    const float* __restrict__ bv)
{
    extern __shared__ __align__(16) char dynsm[];
    __nv_bfloat16* Ah = (__nv_bfloat16*)dynsm;                 // [128][LDA]
    __nv_bfloat16* Kt = Ah + 128 * LDA;                        // [128][LDA] k/v tile
    __shared__ int s_nl[128];
    __shared__ int s_t;
    __shared__ __align__(16) float stg[8][16][STG_LD];         // wide staging 34.8KB

    int tid = threadIdx.x, w = tid >> 5, lane = tid & 31;
    if (tid < 128) s_nl[tid] = g_nlist[blockIdx.x * 128 + tid];
    __syncthreads();
    if (tid == 0) {
        int t = -1;
        for (int m = 0; m < 128; m++) if (s_nl[m] >= 0) { t = ntype[s_nl[m]]; break; }
        s_t = t;
    }
    __syncthreads();
    if (s_t < 0) return;

    // stage A: gather x rows -> bf16
    for (int idx = tid; idx < 128 * 32; idx += 256) {
        int m = idx >> 5, c = (idx & 31) * 4;
        int n = s_nl[m];
        float4 f = (n >= 0) ? *(const float4*)(x + (size_t)n * FDIM + c)
                            : make_float4(0.f, 0.f, 0.f, 0.f);
        *(uint32_t*)(Ah + m * LDA + c)     = f2bf2(f.x, f.y);
        *(uint32_t*)(Ah + m * LDA + c + 2) = f2bf2(f.z, f.w);
    }
    __syncthreads();

    int rg = w & 3, cg = w >> 2;
    int row_m = rg * 32;
    int colb = cg * 64;

    for (int set = 0; set < 3; set++) {
        const __nv_bfloat16* GBh = (const __nv_bfloat16*)(g_wB + (size_t)(s_t * 4 + set) * 65536);

        wmma::fragment<wmma::accumulator, 16, 16, 16, float> acc[2][4];
        #pragma unroll
        for (int mi = 0; mi < 2; mi++)
            #pragma unroll
            for (int ni = 0; ni < 4; ni++) wmma::fill_fragment(acc[mi][ni], 0.f);

        #pragma unroll
        for (int k = 0; k < 8; k++) {
            wmma::fragment<wmma::matrix_a, 16, 16, 16, __nv_bfloat16, wmma::row_major> ah0, ah1;
            wmma::load_matrix_sync(ah0, Ah + (row_m +  0) * LDA + k * 16, LDA);
            wmma::load_matrix_sync(ah1, Ah + (row_m + 16) * LDA + k * 16, LDA);
            #pragma unroll
            for (int ni = 0; ni < 4; ni++) {
                wmma::fragment<wmma::matrix_b, 16, 16, 16, __nv_bfloat16, wmma::row_major> bh;
                wmma::load_matrix_sync(bh, GBh + (k * 16) * 128 + colb + ni * 16, 128);
                wmma::mma_sync(acc[0][ni], ah0, bh, acc[0][ni]);
                wmma::mma_sync(acc[1][ni], ah1, bh, acc[1][ni]);
            }
        }

        const float* bias = ((set == 0) ? bk : (set == 1) ? bq : bv) + s_t * FDIM;

        if (set == 1) {
            // q epilogue: batch 4 tiles -> wide staging -> one 64B write per lane
            #pragma unroll
            for (int mi = 0; mi < 2; mi++) {
                #pragma unroll
                for (int ni = 0; ni < 4; ni++)
                    wmma::store_matrix_sync(&stg[w][0][ni * 16], acc[mi][ni], STG_LD, wmma::mem_row_major);
                __syncwarp();
                int grow = lane >> 1, ghalf = lane & 1;
                int gr = s_nl[row_m + mi * 16 + grow];
                if (gr >= 0) {
                    const float* Sr = &stg[w][grow][ghalf * 32];
                    __nv_bfloat16* drow = g_qb + (size_t)gr * FDIM + colb + ghalf * 32;
                    const float* bb = bias + colb + ghalf * 32;
                    #pragma unroll
                    for (int u = 0; u < 4; u++) {
                        float4 f0 = *(const float4*)(Sr + u * 8);
                        float4 f1 = *(const float4*)(Sr + u * 8 + 4);
                        float4 b0 = *(const float4*)(bb + u * 8);
                        float4 b1 = *(const float4*)(bb + u * 8 + 4);
                        f0.x += b0.x; f0.y += b0.y; f0.z += b0.z; f0.w += b0.w;
                        f1.x += b1.x; f1.y += b1.y; f1.z += b1.z; f1.w += b1.w;
                        *(uint4*)(drow + u * 8) = make_uint4(f2bf2(f0.x, f0.y), f2bf2(f0.z, f0.w),
                                                             f2bf2(f1.x, f1.y), f2bf2(f1.z, f1.w));
                    }
                }
                __syncwarp();
            }
        } else {
            // k/v epilogue: batch 4 tiles -> staging -> bias -> warp-local Kt
            #pragma unroll
            for (int mi = 0; mi < 2; mi++) {
                #pragma unroll
                for (int ni = 0; ni < 4; ni++)
                    wmma::store_matrix_sync(&stg[w][0][ni * 16], acc[mi][ni], STG_LD, wmma::mem_row_major);
                __syncwarp();
                int grow = lane >> 1, ghalf = lane & 1;
                int m = row_m + mi * 16 + grow;
                const float* Sr = &stg[w][grow][ghalf * 32];
                const float* bb = bias + colb + ghalf * 32;
                __nv_bfloat16* drow = Kt + m * LDA + colb + ghalf * 32;
                #pragma unroll
                for (int u = 0; u < 4; u++) {
                    float4 f0 = *(const float4*)(Sr + u * 8);
                    float4 f1 = *(const float4*)(Sr + u * 8 + 4);
                    float4 b0 = *(const float4*)(bb + u * 8);
                    float4 b1 = *(const float4*)(bb + u * 8 + 4);
                    f0.x += b0.x; f0.y += b0.y; f0.z += b0.z; f0.w += b0.w;
                    f1.x += b1.x; f1.y += b1.y; f1.z += b1.z; f1.w += b1.w;
                    *(uint4*)(drow + u * 8) = make_uint4(f2bf2(f0.x, f0.y), f2bf2(f0.z, f0.w),
                                                         f2bf2(f1.x, f1.y), f2bf2(f1.z, f1.w));
                }
                __syncwarp();
            }

            // fused table phase: hoist A-frags (load once per row-tile, reuse across r)
            const __nv_bfloat16* relb = (set == 0) ? g_relab : g_relmb;
            __nv_bfloat16* dstt = (set == 0) ? g_kt : g_vt;
            #pragma unroll
            for (int mi = 0; mi < 2; mi++) {
                wmma::fragment<wmma::matrix_a, 16, 16, 16, __nv_bfloat16, wmma::row_major> af[4];
                #pragma unroll
                for (int hi = 0; hi < 4; hi++)
                    wmma::load_matrix_sync(af[hi], Kt + (row_m + mi * 16) * LDA + (cg * 4 + hi) * 16, LDA);
                int grow = lane >> 1, ghalf = lane & 1;
                int gr = s_nl[row_m + mi * 16 + grow];
                for (int r5 = 0; r5 < RR; r5++) {
                    wmma::fragment<wmma::accumulator, 16, 16, 16, float> tacc[4];
                    #pragma unroll
                    for (int hi = 0; hi < 4; hi++) {
                        int head = cg * 4 + hi;
                        wmma::fragment<wmma::matrix_b, 16, 16, 16, __nv_bfloat16, wmma::row_major> bf;
                        wmma::load_matrix_sync(bf, relb + (r5 * HH + head) * 256, 16);
                        wmma::fill_fragment(tacc[hi], 0.f);
                        wmma::mma_sync(tacc[hi], af[hi], bf, tacc[hi]);
                    }
                    #pragma unroll
                    for (int hi = 0; hi < 4; hi++)
                        wmma::store_matrix_sync(&stg[w][0][hi * 16], tacc[hi], STG_LD, wmma::mem_row_major);
                    __syncwarp();
                    if (gr >= 0) {
                        const float* Sr = &stg[w][grow][ghalf * 32];
                        __nv_bfloat16* drow = dstt + ((size_t)gr * RR + r5) * FDIM + colb + ghalf * 32;
                        #pragma unroll
                        for (int u = 0; u < 4; u++) {
                            float4 f0 = *(const float4*)(Sr + u * 8);
                            float4 f1 = *(const float4*)(Sr + u * 8 + 4);
                            *(uint4*)(drow + u * 8) = make_uint4(f2bf2(f0.x, f0.y), f2bf2(f0.z, f0.w),
                                                                 f2bf2(f1.x, f1.y), f2bf2(f1.z, f1.w));
                        }
                    }
                    __syncwarp();
                }
            }
            __syncwarp();   // Kt reads done before next set overwrites (warp-local)
        }
    }
}

// ============================================================================
// K4: edge scores. Half-warp per edge, unroll x2.          [PROFILED SLOT #4]
// ============================================================================
__global__ __launch_bounds__(256) void score2_kernel(
    const int* __restrict__ src, const int* __restrict__ dst,
    const int* __restrict__ etype, const float* __restrict__ rel_pri, int E) {
    __shared__ float s_pri[RR * HH];
    if (threadIdx.x < RR * HH) s_pri[threadIdx.x] = rel_pri[threadIdx.x] * (1.0f / SQRT_DK);
    __syncthreads();

    int warp = threadIdx.x >> 5;
    int lane = threadIdx.x & 31;
    int sub = lane >> 4;
    int l = lane & 15;
    int h = l >> 1, half = l & 1;
    int off = h * DKK + half * 8;

    int base = (blockIdx.x * 8 + warp) * 4;
    int stride = gridDim.x * 32;
    for (int e0 = base; e0 < E; e0 += stride) {
        int eA = e0 + sub * 2;
        int eB = eA + 1;
        bool vA = (eA < E), vB = (eB < E);
        int ecA = vA ? eA : (E - 1);
        int ecB = vB ? eB : (E - 1);
        int sA = src[ecA], dA = dst[ecA], rA = etype[ecA];
        int sB = src[ecB], dB = dst[ecB], rB = etype[ecB];
        uint4 kuA = *(const uint4*)(g_kt + ((size_t)sA * RR + rA) * FDIM + off);
        uint4 quA = *(const uint4*)(g_qb + (size_t)dA * FDIM + off);
        uint4 kuB = *(const uint4*)(g_kt + ((size_t)sB * RR + rB) * FDIM + off);
        uint4 quB = *(const uint4*)(g_qb + (size_t)dB * FDIM + off);
        float scA = dot8(kuA, quA);
        float scB = dot8(kuB, quB);
        scA += __shfl_xor_sync(0xFFFFFFFFu, scA, 1);
        scB += __shfl_xor_sync(0xFFFFFFFFu, scB, 1);
        scA *= s_pri[rA * HH + h];
        scB *= s_pri[rB * HH + h];
        if (half == 0) {
            if (vA) {
                float p = __expf(scA);
                g_a[eA * HH + h] = p;
                atomicAdd(&g_den[(dA * RR + rA) * HH + h], p);
            }
            if (vB) {
                float p = __expf(scB);
                g_a[eB * HH + h] = p;
                atomicAdd(&g_den[(dB * RR + rB) * HH + h], p);
            }
        }
    }
}

// ============================================================================
// K5: aggregation. Half-warp per edge, unroll x2.
// ============================================================================
__global__ __launch_bounds__(256) void agg2_kernel(
    const int* __restrict__ src, const int* __restrict__ dst,
    const int* __restrict__ etype, int E) {
    int warp = threadIdx.x >> 5;
    int lane = threadIdx.x & 31;
    int sub = lane >> 4;
    int l = lane & 15;
    int h = l >> 1, half = l & 1;
    int off = h * DKK + half * 8;

    int base = (blockIdx.x * 8 + warp) * 4;
    int stride = gridDim.x * 32;
    for (int e0 = base; e0 < E; e0 += stride) {
        int eA = e0 + sub * 2;
        int eB = eA + 1;
        bool vA = (eA < E), vB = (eB < E);
        int ecA = vA ? eA : (E - 1);
        int ecB = vB ? eB : (E - 1);
        int sA = src[ecA], dA = dst[ecA], rA = etype[ecA];
        int sB = src[ecB], dB = dst[ecB], rB = etype[ecB];
        float pA = g_a[ecA * HH + h];
        float pB = g_a[ecB * HH + h];
        uint4 vuA = *(const uint4*)(g_vt + ((size_t)sA * RR + rA) * FDIM + off);
        uint4 vuB = *(const uint4*)(g_vt + ((size_t)sB * RR + rB) * FDIM + off);
        float denA = g_den[(dA * RR + rA) * HH + h];
        float denB = g_den[(dB * RR + rB) * HH + h];
        float awA = pA / denA;
        float awB = pB / denB;
        if (vA) {
            float2 v0 = bf2f2(vuA.x), v1 = bf2f2(vuA.y), v2 = bf2f2(vuA.z), v3 = bf2f2(vuA.w);
            float* dp = g_acc + (size_t)dA * FDIM + off;
            atomicAdd((float4*)dp,       make_float4(awA*v0.x, awA*v0.y, awA*v1.x, awA*v1.y));
            atomicAdd((float4*)(dp + 4), make_float4(awA*v2.x, awA*v2.y, awA*v3.x, awA*v3.y));
        }
        if (vB) {
            float2 v0 = bf2f2(vuB.x), v1 = bf2f2(vuB.y), v2 = bf2f2(vuB.z), v3 = bf2f2(vuB.w);
            float* dp = g_acc + (size_t)dB * FDIM + off;
            atomicAdd((float4*)dp,       make_float4(awB*v0.x, awB*v0.y, awB*v1.x, awB*v1.y));
            atomicAdd((float4*)(dp + 4), make_float4(awB*v2.x, awB*v2.y, awB*v3.x, awB*v3.y));
        }
    }
}

// ============================================================================
// K6: mean-over-etypes, Wa proj (wmma split-bf16), skip blend, per-type LN
// ============================================================================
__global__ __launch_bounds__(256) void final_wmma_kernel(
    const float* __restrict__ x, const int* __restrict__ ntype,
    const float* __restrict__ ba, const float* __restrict__ skipv,
    const float* __restrict__ ln_g, const float* __restrict__ ln_b,
    float* __restrict__ out)
{
    extern __shared__ __align__(16) char dynsm[];
    __nv_bfloat16* Ah = (__nv_bfloat16*)dynsm;
    __nv_bfloat16* Al = Ah + 128 * LDA;
    float* F = (float*)dynsm;                 // fp32 tile [128][FLD]; aliased AFTER GEMM
    __shared__ int s_nl[128];
    __shared__ int s_t;
    __shared__ float s_scp[128];

    int tid = threadIdx.x, w = tid >> 5, lane = tid & 31;
    if (tid < 128) s_nl[tid] = g_nlist[blockIdx.x * 128 + tid];
    __syncthreads();
    if (tid == 0) {
        int t = -1;
        for (int m = 0; m < 128; m++) if (s_nl[m] >= 0) { t = ntype[s_nl[m]]; break; }
        s_t = t;
    }
    if (tid < 128) {
        int n = s_nl[tid];
        float inv = 1.f;
        if (n >= 0) {
            int cp = 0;
            for (int r = 0; r < RR; r++) cp += (g_den[(n * RR + r) * HH] > 0.f) ? 1 : 0;
            if (cp < 1) cp = 1;
            inv = 1.f / (float)cp;
        }
        s_scp[tid] = inv;
    }
    __syncthreads();
    if (s_t < 0) return;

    for (int idx = tid; idx < 128 * 32; idx += 256) {
        int m = idx >> 5, c = (idx & 31) * 4;
        int n = s_nl[m];
        float4 f = make_float4(0.f, 0.f, 0.f, 0.f);
        if (n >= 0) {
            f = *(const float4*)(g_acc + (size_t)n * FDIM + c);
            float sc = s_scp[m];
            f.x *= sc; f.y *= sc; f.z *= sc; f.w *= sc;
        }
        uint32_t l0, l1;
        uint32_t h0 = bfsplit(f.x, f.y, l0), h1 = bfsplit(f.z, f.w, l1);
        *(uint32_t*)(Ah + m * LDA + c)     = h0;
        *(uint32_t*)(Ah + m * LDA + c + 2) = h1;
        *(uint32_t*)(Al + m * LDA + c)     = l0;
        *(uint32_t*)(Al + m * LDA + c + 2) = l1;
    }
    __syncthreads();

    int rg = w & 3, cg = w >> 2;
    int row_m = rg * 32;
    int colb = cg * 64;
    const __nv_bfloat16* GBh = (const __nv_bfloat16*)(g_wB + (size_t)(s_t * 4 + 3) * 65536);
    const __nv_bfloat16* GBl = GBh + 128 * 128;

    wmma::fragment<wmma::accumulator, 16, 16, 16, float> acc[2][4];
    #pragma unroll
    for (int mi = 0; mi < 2; mi++)
        #pragma unroll
        for (int ni = 0; ni < 4; ni++) wmma::fill_fragment(acc[mi][ni], 0.f);

    #pragma unroll
    for (int k = 0; k < 8; k++) {
        wmma::fragment<wmma::matrix_a, 16, 16, 16, __nv_bfloat16, wmma::row_major> ah0, ah1, al0, al1;
        wmma::load_matrix_sync(ah0, Ah + (row_m +  0) * LDA + k * 16, LDA);
        wmma::load_matrix_sync(ah1, Ah + (row_m + 16) * LDA + k * 16, LDA);
        wmma::load_matrix_sync(al0, Al + (row_m +  0) * LDA + k * 16, LDA);
        wmma::load_matrix_sync(al1, Al + (row_m + 16) * LDA + k * 16, LDA);
        #pragma unroll
        for (int ni = 0; ni < 4; ni++) {
            wmma::fragment<wmma::matrix_b, 16, 16, 16, __nv_bfloat16, wmma::row_major> bh, bl;
            wmma::load_matrix_sync(bh, GBh + (k * 16) * 128 + colb + ni * 16, 128);
            wmma::load_matrix_sync(bl, GBl + (k * 16) * 128 + colb + ni * 16, 128);
            wmma::mma_sync(acc[0][ni], ah0, bh, acc[0][ni]);
            wmma::mma_sync(acc[0][ni], ah0, bl, acc[0][ni]);
            wmma::mma_sync(acc[0][ni], al0, bh, acc[0][ni]);
            wmma::mma_sync(acc[1][ni], ah1, bh, acc[1][ni]);
            wmma::mma_sync(acc[1][ni], ah1, bl, acc[1][ni]);
            wmma::mma_sync(acc[1][ni], al1, bh, acc[1][ni]);
        }
    }
    __syncthreads();

    #pragma unroll
    for (int mi = 0; mi < 2; mi++)
        #pragma unroll
        for (int ni = 0; ni < 4; ni++)
            wmma::store_matrix_sync(F + (row_m + mi * 16) * FLD + colb + ni * 16,
                                    acc[mi][ni], FLD, wmma::mem_row_major);
    __syncthreads();

    float alpha = 1.f / (1.f + __expf(-skipv[s_t]));
    float beta = 1.f - alpha;
    int c0 = lane * 4;
    float4 bav = *(const float4*)(ba   + s_t * FDIM + c0);
    float4 gv  = *(const float4*)(ln_g + s_t * FDIM + c0);
    float4 bv2 = *(const float4*)(ln_b + s_t * FDIM + c0);
    int rbase = w * 16;
    for (int q = 0; q < 16; q++) {
        int m = rbase + q;
        int n = s_nl[m];
        if (n < 0) continue;
        float4 tr = *(float4*)(F + m * FLD + c0);
        float4 xv = *(const float4*)(x + (size_t)n * FDIM + c0);
        float4 v;
        v.x = (tr.x + bav.x) * alpha + xv.x * beta;
        v.y = (tr.y + bav.y) * alpha + xv.y * beta;
        v.z = (tr.z + bav.z) * alpha + xv.z * beta;
        v.w = (tr.w + bav.w) * alpha + xv.w * beta;
        float s  = v.x + v.y + v.z + v.w;
        float s2 = v.x*v.x + v.y*v.y + v.z*v.z + v.w*v.w;
        #pragma unroll
        for (int o = 16; o; o >>= 1) {
            s  += __shfl_xor_sync(0xFFFFFFFFu, s,  o);
            s2 += __shfl_xor_sync(0xFFFFFFFFu, s2, o);
        }
        float mu = s * (1.f / 128.f);
        float var = s2 * (1.f / 128.f) - mu * mu;
        float rstd = rsqrtf(var + 1e-5f);
        float4 ov;
        ov.x = (v.x - mu) * rstd * gv.x + bv2.x;
        ov.y = (v.y - mu) * rstd * gv.y + bv2.y;
        ov.z = (v.z - mu) * rstd * gv.z + bv2.z;
        ov.w = (v.w - mu) * rstd * gv.w + bv2.w;
        *(float4*)(out + (size_t)n * FDIM + c0) = ov;
    }
}

// ---------------- launch ----------------
extern "C" void kernel_launch(void* const* d_in, const int* in_sizes, int n_in,
                              void* d_out, int out_size) {
    const float* x       = (const float*)d_in[0];
    const int*   ntype   = (const int*)  d_in[1];
    const int*   src     = (const int*)  d_in[2];
    const int*   dst     = (const int*)  d_in[3];
    const int*   etype   = (const int*)  d_in[4];
    const float* Wk      = (const float*)d_in[5];
    const float* bk      = (const float*)d_in[6];
    const float* Wq      = (const float*)d_in[7];
    const float* bq      = (const float*)d_in[8];
    const float* Wv      = (const float*)d_in[9];
    const float* bv      = (const float*)d_in[10];
    const float* Wa      = (const float*)d_in[11];
    const float* ba      = (const float*)d_in[12];
    const float* rel_pri = (const float*)d_in[13];
    const float* rel_att = (const float*)d_in[14];
    const float* rel_msg = (const float*)d_in[15];
    const float* skipv   = (const float*)d_in[16];
    const float* ln_g    = (const float*)d_in[17];
    const float* ln_b    = (const float*)d_in[18];
    float* out = (float*)d_out;

    const int N = in_sizes[1];
    const int E = in_sizes[2];
    const int PROJ_SMEM = 2 * 128 * LDA * 2;           // 69632 B (Ah | Kt)
    const int A_SMEM = 2 * 128 * LDA * 2;              // 69632 B
    const int F_SMEM = 128 * FLD * 4;                  // 67584 B
    const int FIN_SMEM = (A_SMEM > F_SMEM) ? A_SMEM : F_SMEM;

    cudaFuncSetAttribute(proj_wmma_kernel,  cudaFuncAttributeMaxDynamicSharedMemorySize, PROJ_SMEM);
    cudaFuncSetAttribute(final_wmma_kernel, cudaFuncAttributeMaxDynamicSharedMemorySize, FIN_SMEM);

    prep_kernel<<<1, 1024>>>(ntype, N);
    combo_kernel<<<2048, 256>>>(ntype, N, Wk, Wq, Wv, Wa, rel_att, rel_msg);
    proj_wmma_kernel<<<NL_CAP / 128, 256, PROJ_SMEM>>>(x, ntype, bk, bq, bv);
    score2_kernel<<<2048, 256>>>(src, dst, etype, rel_pri, E);   // profiled slot #4
    agg2_kernel<<<2048, 256>>>(src, dst, etype, E);
    final_wmma_kernel<<<NL_CAP / 128, 256, FIN_SMEM>>>(x, ntype, ba, skipv, ln_g, ln_b, out);
}